// round 1
// baseline (speedup 1.0000x reference)
#include <cuda_runtime.h>
#include <cstdint>

#define Bn  32
#define ICn 512
#define OCn 512
#define Hn  64
#define Wn  64

typedef unsigned long long ull;

// Scratch (device globals; no allocation allowed)
__device__ float g_style[Bn * ICn];        // style[b,i]
__device__ float g_demod[Bn * OCn];        // demod coefficient d[b,o]
__device__ float g_wsq[OCn * ICn];         // sum over 3x3 of conv_w^2
__device__ float g_wT[ICn * 9 * OCn];      // conv_w transposed to [ic][k][oc]

// ---------------------------------------------------------------------------
// style[b,i] = sqrt(2/512) * sum_k w[b,k] * lin_w[i,k] + lin_b[i]
// ---------------------------------------------------------------------------
__global__ void style_kernel(const float* __restrict__ w,
                             const float* __restrict__ lin_w,
                             const float* __restrict__ lin_b) {
    __shared__ float wv[512];
    int b = blockIdx.x;
    int i = threadIdx.x;
    wv[i] = w[b * 512 + i];
    __syncthreads();
    const float s = sqrtf(2.0f / 512.0f);
    float acc = 0.f;
    const float* lr = lin_w + i * 512;
#pragma unroll 8
    for (int k = 0; k < 512; k++) acc += wv[k] * lr[k];
    g_style[b * 512 + i] = acc * s + lin_b[i];
}

// ---------------------------------------------------------------------------
// Transpose conv_w -> g_wT[(ic*9+k)*512 + oc]; per-(o,i) squared sums -> g_wsq
// ---------------------------------------------------------------------------
__global__ void prep_w_kernel(const float* __restrict__ conv_w) {
    int gid = blockIdx.x * blockDim.x + threadIdx.x;  // gid = oc*512 + ic
    if (gid >= OCn * ICn) return;
    int oc = gid >> 9;
    int ic = gid & 511;
    const float* p = conv_w + (size_t)gid * 9;
    float sq = 0.f;
#pragma unroll
    for (int k = 0; k < 9; k++) {
        float v = p[k];
        sq += v * v;
        g_wT[(ic * 9 + k) * 512 + oc] = v;
    }
    g_wsq[gid] = sq;
}

// ---------------------------------------------------------------------------
// d[b,o] = rsqrt( (2/4608) * sum_i style[b,i]^2 * wsq[o,i] + 1e-8 )
// ---------------------------------------------------------------------------
__global__ void demod_kernel() {
    __shared__ float s2[512];
    int b = blockIdx.x;
    int o = threadIdx.x;
    float sv = g_style[b * 512 + o];
    s2[o] = sv * sv;
    __syncthreads();
    float acc = 0.f;
    const float* wr = g_wsq + o * 512;
#pragma unroll 8
    for (int i = 0; i < 512; i++) acc += s2[i] * wr[i];
    const float c1sq = 2.0f / 4608.0f;
    g_demod[b * 512 + o] = rsqrtf(acc * c1sq + 1e-8f);
}

// ---------------------------------------------------------------------------
// Main conv: per block -> 64 out-channels x (16x16) pixels for one batch.
// Input modulated by style*c1 on SMEM load; output scaled by demod + epilogue.
// Inner product uses packed fma.rn.f32x2 (2 FMAs/instr) over OC pairs.
// ---------------------------------------------------------------------------
#define FMA2(d, a, b_, c_) \
    asm("fma.rn.f32x2 %0, %1, %2, %3;" : "=l"(d) : "l"(a), "l"(b_), "l"(c_))
#define PACK2_BCAST(d, x_) do { \
    unsigned _u = __float_as_uint(x_); \
    asm("mov.b64 %0, {%1, %2};" : "=l"(d) : "r"(_u), "r"(_u)); \
} while (0)

__global__ __launch_bounds__(256) void conv_kernel(
    const float* __restrict__ x, const float* __restrict__ noise,
    const float* __restrict__ bias, const float* __restrict__ noise_w,
    float* __restrict__ out)
{
    __shared__ float xs[8][324];      // 8 ic x 18x18 patch (style-modulated)
    __shared__ float ws[8][9][64];    // 8 ic x 9 taps x 64 oc

    int b   = blockIdx.z;
    int oc0 = blockIdx.y * 64;
    int oy0 = (blockIdx.x >> 2) * 16;
    int ox0 = (blockIdx.x & 3) * 16;

    int t      = threadIdx.x;
    int oc_sub = t >> 5;          // 0..7
    int px_sub = t & 31;          // 0..31
    int ocb    = oc_sub * 8;      // this thread's 8 consecutive oc
    int rb     = px_sub >> 4;     // 0/1
    int cb     = px_sub & 15;     // 0..15
    const float c1 = sqrtf(2.0f / 4608.0f);

    ull acc[8][4];                // [px m][oc-pair j2]
#pragma unroll
    for (int m = 0; m < 8; m++)
#pragma unroll
        for (int j2 = 0; j2 < 4; j2++) acc[m][j2] = 0ULL;

    for (int ic0 = 0; ic0 < 512; ic0 += 8) {
        __syncthreads();
        // --- fill x patch (with style modulation, zero padding) ---
#pragma unroll
        for (int u = 0; u < 11; u++) {            // 11*256 >= 8*324
            int idx = u * 256 + t;
            if (idx < 8 * 324) {
                int ic = idx / 324;
                int p  = idx - ic * 324;
                int r  = p / 18;
                int c  = p - r * 18;
                int gy = oy0 + r - 1, gx = ox0 + c - 1;
                float v = 0.f;
                if ((unsigned)gy < 64u && (unsigned)gx < 64u)
                    v = x[((b * 512 + ic0 + ic) * 64 + gy) * 64 + gx]
                        * (g_style[b * 512 + ic0 + ic] * c1);
                xs[ic][p] = v;
            }
        }
        // --- fill weights (coalesced from transposed layout) ---
#pragma unroll
        for (int u = 0; u < 18; u++) {            // 18*256 == 8*9*64
            int idx  = u * 256 + t;
            int oc   = idx & 63;
            int rest = idx >> 6;                  // = ic*9 + k
            ((float*)ws)[idx] = g_wT[(ic0 * 9 + rest) * 512 + oc0 + oc];
        }
        __syncthreads();

        // --- compute ---
#pragma unroll 1
        for (int ic = 0; ic < 8; ic++) {
#pragma unroll
            for (int kk = 0; kk < 9; kk++) {
                int kh = kk / 3, kw = kk - kh * 3;
                const ull* wq = (const ull*)&ws[ic][kk][ocb];  // 32B aligned
                ull w0 = wq[0], w1 = wq[1], w2 = wq[2], w3 = wq[3];
#pragma unroll
                for (int m = 0; m < 8; m++) {
                    float xv = xs[ic][(rb + 2 * m + kh) * 18 + cb + kw];
                    ull xb;
                    PACK2_BCAST(xb, xv);
                    FMA2(acc[m][0], w0, xb, acc[m][0]);
                    FMA2(acc[m][1], w1, xb, acc[m][1]);
                    FMA2(acc[m][2], w2, xb, acc[m][2]);
                    FMA2(acc[m][3], w3, xb, acc[m][3]);
                }
            }
        }
    }

    // --- epilogue: demod scale + bias + noise injection ---
#pragma unroll
    for (int j2 = 0; j2 < 4; j2++) {
        int oc = oc0 + ocb + 2 * j2;
        float d0 = g_demod[b * 512 + oc], d1 = g_demod[b * 512 + oc + 1];
        float b0 = bias[oc],              b1 = bias[oc + 1];
        float n0 = noise_w[oc],           n1 = noise_w[oc + 1];
#pragma unroll
        for (int m = 0; m < 8; m++) {
            int y    = oy0 + rb + 2 * m;
            int xc   = ox0 + cb;
            int base = ((b * 512 + oc) * 64 + y) * 64 + xc;
            unsigned lo_u, hi_u;
            asm("mov.b64 {%0, %1}, %2;" : "=r"(lo_u), "=r"(hi_u) : "l"(acc[m][j2]));
            float lo = __uint_as_float(lo_u);
            float hi = __uint_as_float(hi_u);
            out[base]        = lo * d0 + b0 + n0 * noise[base];
            out[base + 4096] = hi * d1 + b1 + n1 * noise[base + 4096];
        }
    }
}

// ---------------------------------------------------------------------------
// Inputs (metadata order): x, w, conv_w, lin_w, lin_b, bias, noise_w, noise
// ---------------------------------------------------------------------------
extern "C" void kernel_launch(void* const* d_in, const int* in_sizes, int n_in,
                              void* d_out, int out_size) {
    (void)in_sizes; (void)n_in; (void)out_size;
    const float* x       = (const float*)d_in[0];
    const float* w       = (const float*)d_in[1];
    const float* conv_w  = (const float*)d_in[2];
    const float* lin_w   = (const float*)d_in[3];
    const float* lin_b   = (const float*)d_in[4];
    const float* bias    = (const float*)d_in[5];
    const float* noise_w = (const float*)d_in[6];
    const float* noise   = (const float*)d_in[7];
    float* out = (float*)d_out;

    style_kernel<<<Bn, 512>>>(w, lin_w, lin_b);
    prep_w_kernel<<<(OCn * ICn + 255) / 256, 256>>>(conv_w);
    demod_kernel<<<Bn, 512>>>();

    dim3 grid(16, OCn / 64, Bn);   // (4x4 spatial tiles, 8 oc tiles, 32 batch)
    conv_kernel<<<grid, 256>>>(x, noise, bias, noise_w, out);
}

// round 5
// speedup vs baseline: 2.1191x; 2.1191x over previous
#include <cuda_runtime.h>
#include <cuda_bf16.h>
#include <cstdint>

#define Bn  32
#define ICn 512
#define OCn 512

// ---------------- device scratch (no allocation allowed) ----------------
__device__ float g_style[Bn * ICn];
__device__ float g_demod[Bn * OCn];
__device__ float g_wsq[OCn * ICn];
// weight tiles: [144 chunks][512 oc][32 k] bf16 (k contiguous), c1 pre-applied
__device__ __align__(16) __nv_bfloat16 g_mwhi[144 * 512 * 32];
__device__ __align__(16) __nv_bfloat16 g_mwlo[144 * 512 * 32];

// ---------------- small prep kernels ----------------
__global__ void style_kernel(const float* __restrict__ w, const float* __restrict__ lin_w,
                             const float* __restrict__ lin_b) {
    __shared__ float wv[512];
    int b = blockIdx.x, i = threadIdx.x;
    wv[i] = w[b * 512 + i];
    __syncthreads();
    float acc = 0.f;
    const float* lr = lin_w + i * 512;
#pragma unroll 8
    for (int k = 0; k < 512; k++) acc += wv[k] * lr[k];
    g_style[b * 512 + i] = acc * (1.0f / 16.0f) + lin_b[i];   // sqrt(2/512)=1/16
}

__global__ void prep_wsq_kernel(const float* __restrict__ conv_w) {
    int gid = blockIdx.x * blockDim.x + threadIdx.x;   // oc*512 + ic
    if (gid >= OCn * ICn) return;
    const float* p = conv_w + (size_t)gid * 9;
    float sq = 0.f;
#pragma unroll
    for (int k = 0; k < 9; k++) { float v = p[k]; sq += v * v; }
    g_wsq[gid] = sq;
}

__global__ void demod_kernel() {
    __shared__ float s2[512];
    int b = blockIdx.x, o = threadIdx.x;
    float sv = g_style[b * 512 + o];
    s2[o] = sv * sv;
    __syncthreads();
    float acc = 0.f;
    const float* wr = g_wsq + o * 512;
#pragma unroll 8
    for (int i = 0; i < 512; i++) acc += s2[i] * wr[i];
    // demod = rsqrt(c1^2 * sum_i style^2 * wsq + 1e-8),  c1^2 = 2/4608 = 1/2304
    g_demod[b * 512 + o] = rsqrtf(acc * (1.0f / 2304.0f) + 1e-8f);
}

// weight prep: hi/lo bf16 split, c1 = 1/48 applied ONCE here
__global__ void prep_mw_kernel(const float* __restrict__ conv_w) {
    int gid = blockIdx.x * blockDim.x + threadIdx.x;
    if (gid >= 144 * 512 * 32) return;
    int icl = gid & 31;
    int oc  = (gid >> 5) & 511;
    int chunk = gid >> 14;
    int icb = chunk / 9, tap = chunk - icb * 9;
    float v = conv_w[((size_t)oc * 512 + icb * 32 + icl) * 9 + tap] * (1.0f / 48.0f);
    __nv_bfloat16 hi = __float2bfloat16(v);
    g_mwhi[gid] = hi;
    g_mwlo[gid] = __float2bfloat16(v - __bfloat162float(hi));
}

// ---------------- main conv (mma.sync implicit GEMM) ----------------
#define MMA16816(d, a, b0_, b1_) \
    asm volatile("mma.sync.aligned.m16n8k16.row.col.f32.bf16.bf16.f32 " \
        "{%0,%1,%2,%3}, {%4,%5,%6,%7}, {%8,%9}, {%0,%1,%2,%3};" \
        : "+f"((d)[0]), "+f"((d)[1]), "+f"((d)[2]), "+f"((d)[3]) \
        : "r"((a)[0]), "r"((a)[1]), "r"((a)[2]), "r"((a)[3]), "r"(b0_), "r"(b1_))

#define AST 40   // smem row stride in bf16 elements (80 bytes)

__device__ __forceinline__ uint32_t lds_pair(const __nv_bfloat16* base, int row, int k) {
    return *(const uint32_t*)((const char*)base + (row * AST + k) * 2);
}

__global__ void __launch_bounds__(256) conv_hmma_kernel(
    const float* __restrict__ x, const float* __restrict__ noise,
    const float* __restrict__ bias, const float* __restrict__ noise_w,
    float* __restrict__ out)
{
    __shared__ __align__(16) __nv_bfloat16 sAhi[128 * AST];
    __shared__ __align__(16) __nv_bfloat16 sAlo[128 * AST];
    __shared__ __align__(16) __nv_bfloat16 sBhi[128 * AST];
    __shared__ __align__(16) __nv_bfloat16 sBlo[128 * AST];
    __shared__ float sstyle[512];

    const int tid  = threadIdx.x;
    const int lane = tid & 31, wid = tid >> 5;
    const int b   = blockIdx.z;
    const int oc0 = blockIdx.y * 128;
    const int y0  = blockIdx.x * 2;

    for (int i = tid; i < 512; i += 256)
        sstyle[i] = g_style[b * 512 + i];           // c1 NOT applied here
    // (first __syncthreads in the chunk loop orders this before use)

    float acc[4][4][4];
#pragma unroll
    for (int a = 0; a < 4; a++)
#pragma unroll
        for (int c = 0; c < 4; c++)
#pragma unroll
            for (int r = 0; r < 4; r++) acc[a][c][r] = 0.f;

    const int p = tid & 127, khalf = tid >> 7;      // A-build role
    const int py = p >> 6, px = p & 63;
    const int wm = wid >> 2, wn = wid & 3;          // warp tile: 64 m x 32 n
    const int gr = lane >> 2, tg = lane & 3;        // fragment lane coords

    for (int icb = 0; icb < 16; icb++) {
        for (int tap = 0; tap < 9; tap++) {
            __syncthreads();   // previous chunk's fragment reads done
            const int kh = tap / 3, kw = tap - kh * 3;
            const int gy = y0 + py + kh - 1, gx = px + kw - 1;
            const bool ok = ((unsigned)gy < 64u) && ((unsigned)gx < 64u);

            // ---- A build: im2col + style modulation + hi/lo split ----
            {
                const float* xp = x + ((size_t)(b * 512 + icb * 32 + khalf * 16) << 12)
                                    + gy * 64 + gx;
                int icl = khalf * 16;
                uint32_t* dsth = (uint32_t*)(sAhi + p * AST + icl);
                uint32_t* dstl = (uint32_t*)(sAlo + p * AST + icl);
#pragma unroll
                for (int j = 0; j < 8; j++) {
                    float v0 = ok ? xp[0]    * sstyle[icb * 32 + icl]     : 0.f;
                    float v1 = ok ? xp[4096] * sstyle[icb * 32 + icl + 1] : 0.f;
                    __nv_bfloat16 h0 = __float2bfloat16(v0);
                    __nv_bfloat16 h1 = __float2bfloat16(v1);
                    __nv_bfloat16 l0 = __float2bfloat16(v0 - __bfloat162float(h0));
                    __nv_bfloat16 l1 = __float2bfloat16(v1 - __bfloat162float(h1));
                    dsth[j] = ((uint32_t)__bfloat16_as_ushort(h1) << 16) | __bfloat16_as_ushort(h0);
                    dstl[j] = ((uint32_t)__bfloat16_as_ushort(l1) << 16) | __bfloat16_as_ushort(l0);
                    icl += 2; xp += 8192;
                }
            }
            // ---- B copy: [128 oc][32 k] bf16, coalesced uint4 ----
            {
                const int chunk = icb * 9 + tap;
                const uint4* gh = (const uint4*)(g_mwhi + ((size_t)(chunk * 512 + oc0) * 32));
                const uint4* gl = (const uint4*)(g_mwlo + ((size_t)(chunk * 512 + oc0) * 32));
#pragma unroll
                for (int q = 0; q < 2; q++) {
                    int i4 = tid * 2 + q;            // 512 uint4 per buffer
                    int row = i4 >> 2, seg = i4 & 3;
                    *(uint4*)((char*)sBhi + row * 80 + seg * 16) = gh[i4];
                    *(uint4*)((char*)sBlo + row * 80 + seg * 16) = gl[i4];
                }
            }
            __syncthreads();

            // ---- fragments via direct LDS + 3-pass mma ----
#pragma unroll
            for (int ks = 0; ks < 2; ks++) {
                const int kb = ks * 16;
                uint32_t ah[4][4], al[4][4], bh[4][2], bl[4][2];
#pragma unroll
                for (int mi = 0; mi < 4; mi++) {
                    int r0 = wm * 64 + mi * 16 + gr;
                    ah[mi][0] = lds_pair(sAhi, r0,     kb + tg * 2);
                    ah[mi][1] = lds_pair(sAhi, r0 + 8, kb + tg * 2);
                    ah[mi][2] = lds_pair(sAhi, r0,     kb + tg * 2 + 8);
                    ah[mi][3] = lds_pair(sAhi, r0 + 8, kb + tg * 2 + 8);
                    al[mi][0] = lds_pair(sAlo, r0,     kb + tg * 2);
                    al[mi][1] = lds_pair(sAlo, r0 + 8, kb + tg * 2);
                    al[mi][2] = lds_pair(sAlo, r0,     kb + tg * 2 + 8);
                    al[mi][3] = lds_pair(sAlo, r0 + 8, kb + tg * 2 + 8);
                }
#pragma unroll
                for (int ni = 0; ni < 4; ni++) {
                    int n0 = wn * 32 + ni * 8 + gr;
                    bh[ni][0] = lds_pair(sBhi, n0, kb + tg * 2);
                    bh[ni][1] = lds_pair(sBhi, n0, kb + tg * 2 + 8);
                    bl[ni][0] = lds_pair(sBlo, n0, kb + tg * 2);
                    bl[ni][1] = lds_pair(sBlo, n0, kb + tg * 2 + 8);
                }
#pragma unroll
                for (int mi = 0; mi < 4; mi++)
#pragma unroll
                    for (int ni = 0; ni < 4; ni++) {
                        MMA16816(acc[mi][ni], ah[mi], bh[ni][0], bh[ni][1]);  // hi*hi
                        MMA16816(acc[mi][ni], ah[mi], bl[ni][0], bl[ni][1]);  // hi*lo
                        MMA16816(acc[mi][ni], al[mi], bh[ni][0], bh[ni][1]);  // lo*hi
                    }
            }
        }
    }

    // ---- epilogue: demod + bias + noise ----
#pragma unroll
    for (int mi = 0; mi < 4; mi++)
#pragma unroll
        for (int ni = 0; ni < 4; ni++) {
            int oc = oc0 + wn * 32 + ni * 8 + tg * 2;
            int m  = wm * 64 + mi * 16 + gr;
            float dm0 = g_demod[b * 512 + oc],  dm1 = g_demod[b * 512 + oc + 1];
            float bs0 = bias[oc],               bs1 = bias[oc + 1];
            float nw0 = noise_w[oc],            nw1 = noise_w[oc + 1];
#pragma unroll
            for (int rr = 0; rr < 2; rr++) {
                int mm = m + rr * 8;                        // c0/c1 row, c2/c3 row+8
                int yy = y0 + (mm >> 6), xx = mm & 63;
                size_t i0 = ((size_t)(b * 512 + oc) << 12) + yy * 64 + xx;
                size_t i1 = i0 + 4096;                      // next oc
                out[i0] = acc[mi][ni][rr * 2 + 0] * dm0 + bs0 + nw0 * noise[i0];
                out[i1] = acc[mi][ni][rr * 2 + 1] * dm1 + bs1 + nw1 * noise[i1];
            }
        }
}

// ---------------------------------------------------------------------------
// Inputs (metadata order): x, w, conv_w, lin_w, lin_b, bias, noise_w, noise
// ---------------------------------------------------------------------------
extern "C" void kernel_launch(void* const* d_in, const int* in_sizes, int n_in,
                              void* d_out, int out_size) {
    (void)in_sizes; (void)n_in; (void)out_size;
    const float* x       = (const float*)d_in[0];
    const float* w       = (const float*)d_in[1];
    const float* conv_w  = (const float*)d_in[2];
    const float* lin_w   = (const float*)d_in[3];
    const float* lin_b   = (const float*)d_in[4];
    const float* bias    = (const float*)d_in[5];
    const float* noise_w = (const float*)d_in[6];
    const float* noise   = (const float*)d_in[7];
    float* out = (float*)d_out;

    style_kernel<<<Bn, 512>>>(w, lin_w, lin_b);
    prep_wsq_kernel<<<(OCn * ICn + 255) / 256, 256>>>(conv_w);
    demod_kernel<<<Bn, 512>>>();
    prep_mw_kernel<<<(144 * 512 * 32 + 255) / 256, 256>>>(conv_w);

    dim3 grid(32, 4, Bn);   // 32 row-pair tiles x 4 oc tiles x 32 batch
    conv_hmma_kernel<<<grid, 256>>>(x, noise, bias, noise_w, out);
}